// round 6
// baseline (speedup 1.0000x reference)
#include <cuda_runtime.h>
#include <cuda_bf16.h>
#include <cstdint>

// ---------------- problem constants ----------------
#define BATCH 32
#define CIN   256
#define COUT  256
#define HH    49
#define WW    49
#define NPIX  2401
#define NDIR  7
#define NV    1801          // valid hex pixels per batch
#define NVP   1856          // padded to 29*64
#define MTILES 29

// ---------------- GEMM tiling ----------------
#define BM 64
#define BN 256
#define BK 32
#define RS 80                      // smem row stride bytes (32 bf16 = 64B + 16B pad)
#define A_BYTES (BM * RS)          // 5120
#define B_BYTES (BN * RS)          // 20480
#define STAGE   (2 * A_BYTES + 2 * B_BYTES)   // 51200
#define NSTAGE  3
#define SMEM_BYTES (NSTAGE * STAGE)           // 153600
#define NCHUNK  (NDIR * (CIN / BK))           // 56

// ---------------- scratch (static __device__, allocation-guard safe) ----------------
__device__ __align__(16) __nv_bfloat16 g_xt_hi[(size_t)BATCH * NVP * CIN];
__device__ __align__(16) __nv_bfloat16 g_xt_lo[(size_t)BATCH * NVP * CIN];
__device__ __align__(16) __nv_bfloat16 g_w_hi[NDIR * COUT * CIN];
__device__ __align__(16) __nv_bfloat16 g_w_lo[NDIR * COUT * CIN];
__device__ int g_p2h[NVP];

__constant__ int cDY[NDIR] = {0, 1, 0, -1, -1, 0, 1};
__constant__ int cDX[NDIR] = {0, 0, 1,  1,  0, -1, -1};

// ---------------- hex geometry (closed form, no tables needed) ----------------
__device__ __forceinline__ int hx_wmin(int h) { return h < 24 ? 24 - h : 0; }
__device__ __forceinline__ int hx_wmax(int h) { return h < 24 ? 48 : 72 - h; }
__device__ __forceinline__ int hx_rowstart(int h) {
    return (h <= 24) ? (25 * h + (h * (h - 1)) / 2)
                     : (2101 - ((73 - h) * (74 - h)) / 2);
}

// ---------------- PTX helpers (portable sm_80-level) ----------------
__device__ __forceinline__ void cpa16(uint32_t dst, const void* src, int szbytes) {
    asm volatile("cp.async.cg.shared.global [%0], [%1], 16, %2;"
                 :: "r"(dst), "l"(src), "r"(szbytes) : "memory");
}
#define CP_COMMIT() asm volatile("cp.async.commit_group;" ::: "memory")
#define CP_WAIT1()  asm volatile("cp.async.wait_group 1;" ::: "memory")

#define LDSM4(r, addr) \
    asm volatile("ldmatrix.sync.aligned.m8n8.x4.shared.b16 {%0,%1,%2,%3}, [%4];" \
                 : "=r"((r)[0]), "=r"((r)[1]), "=r"((r)[2]), "=r"((r)[3]) : "r"(addr))

#define MMA(d, a, bp) \
    asm volatile("mma.sync.aligned.m16n8k16.row.col.f32.bf16.bf16.f32 " \
                 "{%0,%1,%2,%3}, {%4,%5,%6,%7}, {%8,%9}, {%0,%1,%2,%3};" \
                 : "+f"((d)[0]), "+f"((d)[1]), "+f"((d)[2]), "+f"((d)[3]) \
                 : "r"((a)[0]), "r"((a)[1]), "r"((a)[2]), "r"((a)[3]), \
                   "r"((bp)[0]), "r"((bp)[1]))

// ---------------- init: compact-index -> h table ----------------
__global__ void init_tables() {
    const int h = threadIdx.x;
    if (h < 49) {
        const int s = hx_rowstart(h), e = hx_rowstart(h + 1);
        for (int i = s; i < e; ++i) g_p2h[i] = h;
    }
    if (h == 49)
        for (int i = NV; i < NVP; ++i) g_p2h[i] = 0;
}

// ---------------- zero-fill output (masked pixels must be 0; d_out is poisoned) ----------------
__global__ void zero_out(float4* __restrict__ o, int n4) {
    const int i = blockIdx.x * blockDim.x + threadIdx.x;
    const int stride = gridDim.x * blockDim.x;
    const float4 z = make_float4(0.f, 0.f, 0.f, 0.f);
    for (int k = i; k < n4; k += stride) o[k] = z;
}

// ---------------- preprocessing ----------------
// x [B,C,H,W] fp32 --(hex compact, transpose, bf16 hi/lo split)--> xt [b][cidx][c]
__global__ void split_x_kernel(const float* __restrict__ x) {
    __shared__ float t[32][33];
    const int pt = blockIdx.x, ct = blockIdx.y, b = blockIdx.z;
    const int p00 = pt * 32, c00 = ct * 32;
    const int tx = threadIdx.x & 31;
    const int ty = threadIdx.x >> 5;

#pragma unroll
    for (int k = 0; k < 4; ++k) {
        const int c = c00 + ty + k * 8;
        const int p = p00 + tx;
        float v = 0.f;
        if (p < NPIX) v = x[((size_t)b * CIN + c) * NPIX + p];
        t[ty + k * 8][tx] = v;
    }
    __syncthreads();
#pragma unroll
    for (int k = 0; k < 4; ++k) {
        const int p = p00 + ty + k * 8;
        if (p >= NPIX) continue;
        const int h = p / WW, w = p - (p / WW) * WW;
        if (w < hx_wmin(h) || w > hx_wmax(h)) continue;   // outside hex: drop
        const int cidx = hx_rowstart(h) + w - hx_wmin(h);
        const int c = c00 + tx;
        const float v = t[tx][ty + k * 8];
        const __nv_bfloat16 hi = __float2bfloat16(v);
        const float r = v - __bfloat162float(hi);
        const size_t o = ((size_t)b * NVP + cidx) * CIN + c;
        g_xt_hi[o] = hi;
        g_xt_lo[o] = __float2bfloat16(r);
    }
}

// weight [O,C,7] fp32 -> [n][o][c] bf16 hi/lo
__global__ void split_w_kernel(const float* __restrict__ w) {
    const int idx = blockIdx.x * blockDim.x + threadIdx.x;
    if (idx >= NDIR * COUT * CIN) return;
    const int c = idx & 255;
    const int o = (idx >> 8) & 255;
    const int n = idx >> 16;
    const float v = w[o * (CIN * NDIR) + c * NDIR + n];
    const __nv_bfloat16 hi = __float2bfloat16(v);
    const float r = v - __bfloat162float(hi);
    g_w_hi[idx] = hi;
    g_w_lo[idx] = __float2bfloat16(r);
}

// ---------------- main warp-MMA implicit-GEMM kernel (compacted M) ----------------
__global__ __launch_bounds__(256, 1)
void hexconv_mma(const float* __restrict__ bias, float* __restrict__ out) {
    extern __shared__ char smem[];
    const uint32_t sb = (uint32_t)__cvta_generic_to_shared(smem);
    const int tid  = threadIdx.x;
    const int lane = tid & 31;
    const int wid  = tid >> 5;
    const int wm   = wid & 1;      // 2 M groups of 32
    const int wn   = wid >> 1;     // 4 N groups of 64
    const int p0   = blockIdx.x * BM;   // compact-pixel tile base
    const int b    = blockIdx.y;

    // A-load geometry: thread -> (row am = tid/4, 16B chunk akc = tid%4)
    const int am  = tid >> 2;
    const int akc = tid & 3;
    const int ai  = p0 + am;            // compact index, always < NVP
    const bool aiv = (ai < NV);
    const int ah_ = g_p2h[ai];
    const int aw_ = hx_wmin(ah_) + (ai - hx_rowstart(ah_));

    float acc[2][8][4];
#pragma unroll
    for (int i = 0; i < 2; ++i)
#pragma unroll
        for (int j = 0; j < 8; ++j)
#pragma unroll
            for (int r = 0; r < 4; ++r) acc[i][j][r] = 0.f;

    auto load_chunk = [&](int ch, int s) {
        const int nd = ch >> 3;
        const int c0 = (ch & 7) << 5;
        const uint32_t st = sb + (uint32_t)s * STAGE;
        // A (hi+lo): hex-shifted neighbor, zero-filled when invalid
        const int hh = ah_ + cDY[nd];
        const int ww = aw_ + cDX[nd];
        const bool hv = ((unsigned)hh < HH);
        const int wmn = hv ? hx_wmin(hh) : 0;
        const bool av = aiv && hv && (ww >= wmn) && (ww <= (hv ? hx_wmax(hh) : -1));
        const int src = av ? (hx_rowstart(hh) + ww - wmn) : 0;
        const size_t abase = ((size_t)b * NVP + src) * CIN + c0 + akc * 8;
        const int asz = av ? 16 : 0;
        cpa16(st + am * RS + akc * 16,           g_xt_hi + abase, asz);
        cpa16(st + A_BYTES + am * RS + akc * 16, g_xt_lo + abase, asz);
        // B (hi+lo): row o = tid, 64B contiguous k
        const size_t bbase = ((size_t)nd * COUT + tid) * CIN + c0;
        const uint32_t bdst = st + 2 * A_BYTES + tid * RS;
#pragma unroll
        for (int j = 0; j < 4; ++j) {
            cpa16(bdst + j * 16,           g_w_hi + bbase + j * 8, 16);
            cpa16(bdst + B_BYTES + j * 16, g_w_lo + bbase + j * 8, 16);
        }
    };

    auto compute_chunk = [&](int s) {
        const uint32_t st = sb + (uint32_t)s * STAGE;
        const uint32_t Ah = st;
        const uint32_t Bh = st + 2 * A_BYTES;
#pragma unroll
        for (int ks = 0; ks < 2; ++ks) {
            const int kb = ks * 32;   // 16 bf16 = 32 bytes
            uint32_t ah[2][4], al[2][4], bb[4][4];
            const uint32_t aaddr = Ah + (uint32_t)((wm * 32 + (lane & 15)) * RS)
                                   + kb + ((lane >> 4) << 4);
            LDSM4(ah[0], aaddr);
            LDSM4(ah[1], aaddr + 16 * RS);
            LDSM4(al[0], aaddr + A_BYTES);
            LDSM4(al[1], aaddr + A_BYTES + 16 * RS);
            const uint32_t baddr = Bh + (uint32_t)((wn * 64 + ((lane >> 4) << 3) + (lane & 7)) * RS)
                                   + kb + (((lane >> 3) & 1) << 4);
#pragma unroll
            for (int g = 0; g < 4; ++g) LDSM4(bb[g], baddr + g * 16 * RS);
            // pass 1: acc += Ah*Bh  (each acc touched once -> no dependency chain)
#pragma unroll
            for (int mi = 0; mi < 2; ++mi)
#pragma unroll
                for (int ni = 0; ni < 8; ++ni)
                    MMA(acc[mi][ni], ah[mi], (&bb[ni >> 1][(ni & 1) * 2]));
            // pass 2: acc += Al*Bh
#pragma unroll
            for (int mi = 0; mi < 2; ++mi)
#pragma unroll
                for (int ni = 0; ni < 8; ++ni)
                    MMA(acc[mi][ni], al[mi], (&bb[ni >> 1][(ni & 1) * 2]));
            // reload B = Bl; pass 3: acc += Ah*Bl
#pragma unroll
            for (int g = 0; g < 4; ++g) LDSM4(bb[g], baddr + B_BYTES + g * 16 * RS);
#pragma unroll
            for (int mi = 0; mi < 2; ++mi)
#pragma unroll
                for (int ni = 0; ni < 8; ++ni)
                    MMA(acc[mi][ni], ah[mi], (&bb[ni >> 1][(ni & 1) * 2]));
        }
    };

    // ---------------- 3-stage pipelined mainloop (1 sync per chunk) ----------------
    load_chunk(0, 0); CP_COMMIT();
    load_chunk(1, 1); CP_COMMIT();
    for (int ch = 0; ch < NCHUNK; ++ch) {
        CP_WAIT1();            // group ch complete (ch+1 may be outstanding)
        __syncthreads();       // data visible to all; all done computing stage (ch-1)%3
        if (ch + 2 < NCHUNK) load_chunk(ch + 2, (ch + 2) % NSTAGE);
        CP_COMMIT();           // empty groups near the tail are fine
        compute_chunk(ch % NSTAGE);
    }

    // ---------------- epilogue: bias add (all compacted rows are inside the hex) ----------------
    float bv[16];
#pragma unroll
    for (int ni = 0; ni < 8; ++ni)
#pragma unroll
        for (int j = 0; j < 2; ++j)
            bv[ni * 2 + j] = bias[wn * 64 + ni * 8 + (lane & 3) * 2 + j];

#pragma unroll
    for (int mi = 0; mi < 2; ++mi)
#pragma unroll
        for (int rh = 0; rh < 2; ++rh) {
            const int m = wm * 32 + mi * 16 + (lane >> 2) + rh * 8;
            const int ci = p0 + m;
            if (ci >= NV) continue;
            const int h = g_p2h[ci];
            const int w = hx_wmin(h) + (ci - hx_rowstart(h));
            const int p = h * WW + w;
#pragma unroll
            for (int ni = 0; ni < 8; ++ni)
#pragma unroll
                for (int j = 0; j < 2; ++j) {
                    const int o = wn * 64 + ni * 8 + (lane & 3) * 2 + j;
                    out[((size_t)b * COUT + o) * NPIX + p] =
                        acc[mi][ni][rh * 2 + j] + bv[ni * 2 + j];
                }
        }
}

// ---------------- launch ----------------
extern "C" void kernel_launch(void* const* d_in, const int* in_sizes, int n_in,
                              void* d_out, int out_size) {
    const float* x    = (const float*)d_in[0];
    const float* wgt  = (const float*)d_in[1];
    const float* bias = (const float*)d_in[2];
    float* out = (float*)d_out;
    (void)in_sizes; (void)n_in;

    cudaFuncSetAttribute(hexconv_mma, cudaFuncAttributeMaxDynamicSharedMemorySize, SMEM_BYTES);

    init_tables<<<1, 64>>>();
    zero_out<<<592, 256>>>((float4*)out, out_size / 4);
    split_x_kernel<<<dim3(76, 8, BATCH), 256>>>(x);
    split_w_kernel<<<(NDIR * COUT * CIN + 255) / 256, 256>>>(wgt);

    // compacted implicit GEMM: 29 M-tiles x 32 batches
    hexconv_mma<<<dim3(MTILES, BATCH), 256, SMEM_BYTES>>>(bias, out);
}

// round 7
// speedup vs baseline: 1.1247x; 1.1247x over previous
#include <cuda_runtime.h>
#include <cuda_bf16.h>
#include <cstdint>

// ---------------- problem constants ----------------
#define BATCH 32
#define CIN   256
#define COUT  256
#define HH    49
#define WW    49
#define NPIX  2401
#define NDIR  7
#define NV    1801          // valid hex pixels per batch
#define NVP   1856          // padded to 29*64
#define MTILES 29

// ---------------- GEMM tiling ----------------
#define BM 64
#define BN 256
#define BK 32
#define RS 80                      // smem row stride bytes (32 bf16 = 64B + 16B pad)
#define A_BYTES (BM * RS)          // 5120
#define B_BYTES (BN * RS)          // 20480
#define STAGE   (2 * A_BYTES + 2 * B_BYTES)   // 51200
#define SMEM_BYTES (2 * STAGE)                // 102400  -> 2 CTAs/SM
#define NCHUNK  (NDIR * (CIN / BK))           // 56

// ---------------- scratch (static __device__, allocation-guard safe) ----------------
__device__ __align__(16) __nv_bfloat16 g_xt_hi[(size_t)BATCH * NVP * CIN];
__device__ __align__(16) __nv_bfloat16 g_xt_lo[(size_t)BATCH * NVP * CIN];
__device__ __align__(16) __nv_bfloat16 g_w_hi[NDIR * COUT * CIN];
__device__ __align__(16) __nv_bfloat16 g_w_lo[NDIR * COUT * CIN];
__device__ int g_p2h[NVP];

__constant__ int cDY[NDIR] = {0, 1, 0, -1, -1, 0, 1};
__constant__ int cDX[NDIR] = {0, 0, 1,  1,  0, -1, -1};

// ---------------- hex geometry (closed form) ----------------
__device__ __forceinline__ int hx_wmin(int h) { return h < 24 ? 24 - h : 0; }
__device__ __forceinline__ int hx_wmax(int h) { return h < 24 ? 48 : 72 - h; }
__device__ __forceinline__ int hx_rowstart(int h) {
    return (h <= 24) ? (25 * h + (h * (h - 1)) / 2)
                     : (2101 - ((73 - h) * (74 - h)) / 2);
}

// ---------------- PTX helpers (portable sm_80-level) ----------------
__device__ __forceinline__ void cpa16(uint32_t dst, const void* src, int szbytes) {
    asm volatile("cp.async.cg.shared.global [%0], [%1], 16, %2;"
                 :: "r"(dst), "l"(src), "r"(szbytes) : "memory");
}
#define CP_COMMIT() asm volatile("cp.async.commit_group;" ::: "memory")
#define CP_WAIT1()  asm volatile("cp.async.wait_group 1;" ::: "memory")

#define LDSM4(r, addr) \
    asm volatile("ldmatrix.sync.aligned.m8n8.x4.shared.b16 {%0,%1,%2,%3}, [%4];" \
                 : "=r"((r)[0]), "=r"((r)[1]), "=r"((r)[2]), "=r"((r)[3]) : "r"(addr))

#define MMA(d, a, bp) \
    asm volatile("mma.sync.aligned.m16n8k16.row.col.f32.bf16.bf16.f32 " \
                 "{%0,%1,%2,%3}, {%4,%5,%6,%7}, {%8,%9}, {%0,%1,%2,%3};" \
                 : "+f"((d)[0]), "+f"((d)[1]), "+f"((d)[2]), "+f"((d)[3]) \
                 : "r"((a)[0]), "r"((a)[1]), "r"((a)[2]), "r"((a)[3]), \
                   "r"((bp)[0]), "r"((bp)[1]))

// ---------------- init: compact-index -> h table ----------------
__global__ void init_tables() {
    const int h = threadIdx.x;
    if (h < 49) {
        const int s = hx_rowstart(h), e = hx_rowstart(h + 1);
        for (int i = s; i < e; ++i) g_p2h[i] = h;
    }
    if (h == 49)
        for (int i = NV; i < NVP; ++i) g_p2h[i] = 0;
}

// ---------------- zero-fill output (masked pixels must be 0; d_out poisoned) ----------------
__global__ void zero_out(float4* __restrict__ o, int n4) {
    const int i = blockIdx.x * blockDim.x + threadIdx.x;
    const int stride = gridDim.x * blockDim.x;
    const float4 z = make_float4(0.f, 0.f, 0.f, 0.f);
    for (int k = i; k < n4; k += stride) o[k] = z;
}

// ---------------- preprocessing ----------------
__global__ void split_x_kernel(const float* __restrict__ x) {
    __shared__ float t[32][33];
    const int pt = blockIdx.x, ct = blockIdx.y, b = blockIdx.z;
    const int p00 = pt * 32, c00 = ct * 32;
    const int tx = threadIdx.x & 31;
    const int ty = threadIdx.x >> 5;

#pragma unroll
    for (int k = 0; k < 4; ++k) {
        const int c = c00 + ty + k * 8;
        const int p = p00 + tx;
        float v = 0.f;
        if (p < NPIX) v = x[((size_t)b * CIN + c) * NPIX + p];
        t[ty + k * 8][tx] = v;
    }
    __syncthreads();
#pragma unroll
    for (int k = 0; k < 4; ++k) {
        const int p = p00 + ty + k * 8;
        if (p >= NPIX) continue;
        const int h = p / WW, w = p - (p / WW) * WW;
        if (w < hx_wmin(h) || w > hx_wmax(h)) continue;   // outside hex: drop
        const int cidx = hx_rowstart(h) + w - hx_wmin(h);
        const int c = c00 + tx;
        const float v = t[tx][ty + k * 8];
        const __nv_bfloat16 hi = __float2bfloat16(v);
        const float r = v - __bfloat162float(hi);
        const size_t o = ((size_t)b * NVP + cidx) * CIN + c;
        g_xt_hi[o] = hi;
        g_xt_lo[o] = __float2bfloat16(r);
    }
}

__global__ void split_w_kernel(const float* __restrict__ w) {
    const int idx = blockIdx.x * blockDim.x + threadIdx.x;
    if (idx >= NDIR * COUT * CIN) return;
    const int c = idx & 255;
    const int o = (idx >> 8) & 255;
    const int n = idx >> 16;
    const float v = w[o * (CIN * NDIR) + c * NDIR + n];
    const __nv_bfloat16 hi = __float2bfloat16(v);
    const float r = v - __bfloat162float(hi);
    g_w_hi[idx] = hi;
    g_w_lo[idx] = __float2bfloat16(r);
}

// ---------------- main warp-MMA implicit-GEMM kernel (compacted M, occ=2) ----------------
__global__ __launch_bounds__(256, 2)
void hexconv_mma(const float* __restrict__ bias, float* __restrict__ out) {
    extern __shared__ char smem[];
    const uint32_t sb = (uint32_t)__cvta_generic_to_shared(smem);
    const int tid  = threadIdx.x;
    const int lane = tid & 31;
    const int wid  = tid >> 5;
    const int wm   = wid & 1;      // 2 M groups of 32
    const int wn   = wid >> 1;     // 4 N groups of 64
    const int p0   = blockIdx.x * BM;   // compact-pixel tile base
    const int b    = blockIdx.y;

    // A-load geometry: thread -> (row am = tid/4, 16B chunk akc = tid%4)
    const int am  = tid >> 2;
    const int akc = tid & 3;
    const int ai  = p0 + am;            // compact index (< NVP)
    const bool aiv = (ai < NV);
    const int ah_ = g_p2h[ai];
    const int aw_ = hx_wmin(ah_) + (ai - hx_rowstart(ah_));

    float acc[2][8][4];
#pragma unroll
    for (int i = 0; i < 2; ++i)
#pragma unroll
        for (int j = 0; j < 8; ++j)
#pragma unroll
            for (int r = 0; r < 4; ++r) acc[i][j][r] = 0.f;

    auto load_chunk = [&](int ch, int s) {
        const int nd = ch >> 3;
        const int c0 = (ch & 7) << 5;
        const uint32_t st = sb + (uint32_t)s * STAGE;
        // A (hi+lo): hex-shifted neighbor, zero-filled when invalid
        const int hh = ah_ + cDY[nd];
        const int ww = aw_ + cDX[nd];
        const bool hv = ((unsigned)hh < HH);
        const int wmn = hv ? hx_wmin(hh) : 0;
        const bool av = aiv && hv && (ww >= wmn) && (ww <= (hv ? hx_wmax(hh) : -1));
        const int src = av ? (hx_rowstart(hh) + ww - wmn) : 0;
        const size_t abase = ((size_t)b * NVP + src) * CIN + c0 + akc * 8;
        const int asz = av ? 16 : 0;
        cpa16(st + am * RS + akc * 16,           g_xt_hi + abase, asz);
        cpa16(st + A_BYTES + am * RS + akc * 16, g_xt_lo + abase, asz);
        // B (hi+lo): row o = tid, 64B contiguous k
        const size_t bbase = ((size_t)nd * COUT + tid) * CIN + c0;
        const uint32_t bdst = st + 2 * A_BYTES + tid * RS;
#pragma unroll
        for (int j = 0; j < 4; ++j) {
            cpa16(bdst + j * 16,           g_w_hi + bbase + j * 8, 16);
            cpa16(bdst + B_BYTES + j * 16, g_w_lo + bbase + j * 8, 16);
        }
    };

    auto compute_chunk = [&](int s) {
        const uint32_t st = sb + (uint32_t)s * STAGE;
        const uint32_t Ah = st;
        const uint32_t Bh = st + 2 * A_BYTES;
#pragma unroll
        for (int ks = 0; ks < 2; ++ks) {
            const int kb = ks * 32;   // 16 bf16 = 32 bytes
            uint32_t ah[2][4], al[2][4], bb[4][4];
            const uint32_t aaddr = Ah + (uint32_t)((wm * 32 + (lane & 15)) * RS)
                                   + kb + ((lane >> 4) << 4);
            LDSM4(ah[0], aaddr);
            LDSM4(ah[1], aaddr + 16 * RS);
            LDSM4(al[0], aaddr + A_BYTES);
            LDSM4(al[1], aaddr + A_BYTES + 16 * RS);
            const uint32_t baddr = Bh + (uint32_t)((wn * 64 + ((lane >> 4) << 3) + (lane & 7)) * RS)
                                   + kb + (((lane >> 3) & 1) << 4);
#pragma unroll
            for (int g = 0; g < 4; ++g) LDSM4(bb[g], baddr + g * 16 * RS);
            // pass 1: acc += Ah*Bh  (each acc touched once per pass -> no RAW chain)
#pragma unroll
            for (int mi = 0; mi < 2; ++mi)
#pragma unroll
                for (int ni = 0; ni < 8; ++ni)
                    MMA(acc[mi][ni], ah[mi], (&bb[ni >> 1][(ni & 1) * 2]));
            // pass 2: acc += Al*Bh
#pragma unroll
            for (int mi = 0; mi < 2; ++mi)
#pragma unroll
                for (int ni = 0; ni < 8; ++ni)
                    MMA(acc[mi][ni], al[mi], (&bb[ni >> 1][(ni & 1) * 2]));
            // reload B = Bl; pass 3: acc += Ah*Bl
#pragma unroll
            for (int g = 0; g < 4; ++g) LDSM4(bb[g], baddr + B_BYTES + g * 16 * RS);
#pragma unroll
            for (int mi = 0; mi < 2; ++mi)
#pragma unroll
                for (int ni = 0; ni < 8; ++ni)
                    MMA(acc[mi][ni], ah[mi], (&bb[ni >> 1][(ni & 1) * 2]));
        }
    };

    // ---------------- 2-stage pipelined mainloop ----------------
    load_chunk(0, 0);
    CP_COMMIT();
    for (int ch = 0; ch < NCHUNK; ++ch) {
        if (ch + 1 < NCHUNK) load_chunk(ch + 1, (ch + 1) & 1);
        CP_COMMIT();
        CP_WAIT1();
        __syncthreads();
        compute_chunk(ch & 1);
        __syncthreads();
    }

    // ---------------- epilogue: bias add (all compacted rows inside the hex) ----------------
    float bv[16];
#pragma unroll
    for (int ni = 0; ni < 8; ++ni)
#pragma unroll
        for (int j = 0; j < 2; ++j)
            bv[ni * 2 + j] = bias[wn * 64 + ni * 8 + (lane & 3) * 2 + j];

#pragma unroll
    for (int mi = 0; mi < 2; ++mi)
#pragma unroll
        for (int rh = 0; rh < 2; ++rh) {
            const int m = wm * 32 + mi * 16 + (lane >> 2) + rh * 8;
            const int ci = p0 + m;
            if (ci >= NV) continue;
            const int h = g_p2h[ci];
            const int w = hx_wmin(h) + (ci - hx_rowstart(h));
            const int p = h * WW + w;
#pragma unroll
            for (int ni = 0; ni < 8; ++ni)
#pragma unroll
                for (int j = 0; j < 2; ++j) {
                    const int o = wn * 64 + ni * 8 + (lane & 3) * 2 + j;
                    out[((size_t)b * COUT + o) * NPIX + p] =
                        acc[mi][ni][rh * 2 + j] + bv[ni * 2 + j];
                }
        }
}

// ---------------- launch ----------------
extern "C" void kernel_launch(void* const* d_in, const int* in_sizes, int n_in,
                              void* d_out, int out_size) {
    const float* x    = (const float*)d_in[0];
    const float* wgt  = (const float*)d_in[1];
    const float* bias = (const float*)d_in[2];
    float* out = (float*)d_out;
    (void)in_sizes; (void)n_in;

    cudaFuncSetAttribute(hexconv_mma, cudaFuncAttributeMaxDynamicSharedMemorySize, SMEM_BYTES);

    init_tables<<<1, 64>>>();
    zero_out<<<592, 256>>>((float4*)out, out_size / 4);
    split_x_kernel<<<dim3(76, 8, BATCH), 256>>>(x);
    split_w_kernel<<<(NDIR * COUT * CIN + 255) / 256, 256>>>(wgt);

    // compacted implicit GEMM: 29 M-tiles x 32 batches, 2 CTAs/SM
    hexconv_mma<<<dim3(MTILES, BATCH), 256, SMEM_BYTES>>>(bias, out);
}

// round 8
// speedup vs baseline: 1.8542x; 1.6486x over previous
#include <cuda_runtime.h>
#include <cuda_fp16.h>
#include <cstdint>

// ---------------- problem constants ----------------
#define BATCH 32
#define CIN   256
#define COUT  256
#define HH    49
#define WW    49
#define NPIX  2401
#define NDIR  7
#define NV    1801          // valid hex pixels per batch
#define NVP   1856          // padded to 29*64
#define MTILES 29

// ---------------- GEMM tiling ----------------
#define BM 64
#define BN 256
#define BK 32
#define RS 80                      // smem row stride bytes (32 fp16 = 64B + 16B pad)
#define A_BYTES (BM * RS)          // 5120
#define B_BYTES (BN * RS)          // 20480
#define STAGE   (2 * A_BYTES + B_BYTES)       // 30720 (A_hi, A_lo, B_hi only)
#define NSTAGE  3
#define SMEM_BYTES (NSTAGE * STAGE)           // 92160 -> 2 CTAs/SM (184320 <= 228K)
#define NCHUNK  (NDIR * (CIN / BK))           // 56

// ---------------- scratch (static __device__, allocation-guard safe) ----------------
__device__ __align__(16) __half g_xt_hi[(size_t)BATCH * NVP * CIN];
__device__ __align__(16) __half g_xt_lo[(size_t)BATCH * NVP * CIN];
__device__ __align__(16) __half g_w[NDIR * COUT * CIN];
__device__ int g_p2h[NVP];

__constant__ int cDY[NDIR] = {0, 1, 0, -1, -1, 0, 1};
__constant__ int cDX[NDIR] = {0, 0, 1,  1,  0, -1, -1};

// ---------------- hex geometry (closed form) ----------------
__device__ __forceinline__ int hx_wmin(int h) { return h < 24 ? 24 - h : 0; }
__device__ __forceinline__ int hx_wmax(int h) { return h < 24 ? 48 : 72 - h; }
__device__ __forceinline__ int hx_rowstart(int h) {
    return (h <= 24) ? (25 * h + (h * (h - 1)) / 2)
                     : (2101 - ((73 - h) * (74 - h)) / 2);
}

// ---------------- PTX helpers (portable sm_80-level) ----------------
__device__ __forceinline__ void cpa16(uint32_t dst, const void* src, int szbytes) {
    asm volatile("cp.async.cg.shared.global [%0], [%1], 16, %2;"
                 :: "r"(dst), "l"(src), "r"(szbytes) : "memory");
}
#define CP_COMMIT() asm volatile("cp.async.commit_group;" ::: "memory")
#define CP_WAIT1()  asm volatile("cp.async.wait_group 1;" ::: "memory")

#define LDSM4(r, addr) \
    asm volatile("ldmatrix.sync.aligned.m8n8.x4.shared.b16 {%0,%1,%2,%3}, [%4];" \
                 : "=r"((r)[0]), "=r"((r)[1]), "=r"((r)[2]), "=r"((r)[3]) : "r"(addr))

#define MMA(d, a, bp) \
    asm volatile("mma.sync.aligned.m16n8k16.row.col.f32.f16.f16.f32 " \
                 "{%0,%1,%2,%3}, {%4,%5,%6,%7}, {%8,%9}, {%0,%1,%2,%3};" \
                 : "+f"((d)[0]), "+f"((d)[1]), "+f"((d)[2]), "+f"((d)[3]) \
                 : "r"((a)[0]), "r"((a)[1]), "r"((a)[2]), "r"((a)[3]), \
                   "r"((bp)[0]), "r"((bp)[1]))

// ---------------- init: compact-index -> h table ----------------
__global__ void init_tables() {
    const int h = threadIdx.x;
    if (h < 49) {
        const int s = hx_rowstart(h), e = hx_rowstart(h + 1);
        for (int i = s; i < e; ++i) g_p2h[i] = h;
    }
    if (h == 49)
        for (int i = NV; i < NVP; ++i) g_p2h[i] = 0;
}

// ---------------- zero-fill output (masked pixels must be 0; d_out poisoned) ----------------
__global__ void zero_out(float4* __restrict__ o, int n4) {
    const int i = blockIdx.x * blockDim.x + threadIdx.x;
    const int stride = gridDim.x * blockDim.x;
    const float4 z = make_float4(0.f, 0.f, 0.f, 0.f);
    for (int k = i; k < n4; k += stride) o[k] = z;
}

// ---------------- preprocessing ----------------
// x [B,C,H,W] fp32 --(hex compact, transpose, fp16 hi/lo split)--> xt [b][cidx][c]
__global__ void split_x_kernel(const float* __restrict__ x) {
    __shared__ float t[32][33];
    const int pt = blockIdx.x, ct = blockIdx.y, b = blockIdx.z;
    const int p00 = pt * 32, c00 = ct * 32;
    const int tx = threadIdx.x & 31;
    const int ty = threadIdx.x >> 5;

#pragma unroll
    for (int k = 0; k < 4; ++k) {
        const int c = c00 + ty + k * 8;
        const int p = p00 + tx;
        float v = 0.f;
        if (p < NPIX) v = x[((size_t)b * CIN + c) * NPIX + p];
        t[ty + k * 8][tx] = v;
    }
    __syncthreads();
#pragma unroll
    for (int k = 0; k < 4; ++k) {
        const int p = p00 + ty + k * 8;
        if (p >= NPIX) continue;
        const int h = p / WW, w = p - (p / WW) * WW;
        if (w < hx_wmin(h) || w > hx_wmax(h)) continue;   // outside hex: drop
        const int cidx = hx_rowstart(h) + w - hx_wmin(h);
        const int c = c00 + tx;
        const float v = t[tx][ty + k * 8];
        const __half hi = __float2half(v);
        const float r = v - __half2float(hi);
        const size_t o = ((size_t)b * NVP + cidx) * CIN + c;
        g_xt_hi[o] = hi;
        g_xt_lo[o] = __float2half(r);
    }
}

// weight [O,C,7] fp32 -> [n][o][c] fp16 (single rounding; error 2^-12 RMS)
__global__ void split_w_kernel(const float* __restrict__ w) {
    const int idx = blockIdx.x * blockDim.x + threadIdx.x;
    if (idx >= NDIR * COUT * CIN) return;
    const int c = idx & 255;
    const int o = (idx >> 8) & 255;
    const int n = idx >> 16;
    g_w[idx] = __float2half(w[o * (CIN * NDIR) + c * NDIR + n]);
}

// ---------------- main warp-MMA implicit-GEMM kernel (compacted M, 2-pass fp16) ----------------
__global__ __launch_bounds__(256, 2)
void hexconv_mma(const float* __restrict__ bias, float* __restrict__ out) {
    extern __shared__ char smem[];
    const uint32_t sb = (uint32_t)__cvta_generic_to_shared(smem);
    const int tid  = threadIdx.x;
    const int lane = tid & 31;
    const int wid  = tid >> 5;
    const int wm   = wid & 1;      // 2 M groups of 32
    const int wn   = wid >> 1;     // 4 N groups of 64
    const int p0   = blockIdx.x * BM;   // compact-pixel tile base
    const int b    = blockIdx.y;

    // A-load geometry: thread -> (row am = tid/4, 16B chunk akc = tid%4)
    const int am  = tid >> 2;
    const int akc = tid & 3;
    const int ai  = p0 + am;            // compact index (< NVP)
    const bool aiv = (ai < NV);
    const int ah_ = g_p2h[ai];
    const int aw_ = hx_wmin(ah_) + (ai - hx_rowstart(ah_));

    float acc[2][8][4];
#pragma unroll
    for (int i = 0; i < 2; ++i)
#pragma unroll
        for (int j = 0; j < 8; ++j)
#pragma unroll
            for (int r = 0; r < 4; ++r) acc[i][j][r] = 0.f;

    auto load_chunk = [&](int ch, int s) {
        const int nd = ch >> 3;
        const int c0 = (ch & 7) << 5;
        const uint32_t st = sb + (uint32_t)s * STAGE;
        // A (hi+lo): hex-shifted neighbor, zero-filled when invalid
        const int hh = ah_ + cDY[nd];
        const int ww = aw_ + cDX[nd];
        const bool hv = ((unsigned)hh < HH);
        const int wmn = hv ? hx_wmin(hh) : 0;
        const bool av = aiv && hv && (ww >= wmn) && (ww <= (hv ? hx_wmax(hh) : -1));
        const int src = av ? (hx_rowstart(hh) + ww - wmn) : 0;
        const size_t abase = ((size_t)b * NVP + src) * CIN + c0 + akc * 8;
        const int asz = av ? 16 : 0;
        cpa16(st + am * RS + akc * 16,           g_xt_hi + abase, asz);
        cpa16(st + A_BYTES + am * RS + akc * 16, g_xt_lo + abase, asz);
        // B: row o = tid, 64B contiguous k
        const size_t bbase = ((size_t)nd * COUT + tid) * CIN + c0;
        const uint32_t bdst = st + 2 * A_BYTES + tid * RS;
#pragma unroll
        for (int j = 0; j < 4; ++j)
            cpa16(bdst + j * 16, g_w + bbase + j * 8, 16);
    };

    auto compute_chunk = [&](int s) {
        const uint32_t st = sb + (uint32_t)s * STAGE;
        const uint32_t Ah = st;
        const uint32_t Bh = st + 2 * A_BYTES;
#pragma unroll
        for (int ks = 0; ks < 2; ++ks) {
            const int kb = ks * 32;   // 16 fp16 = 32 bytes
            uint32_t ah[2][4], al[2][4], bb[4][4];
            const uint32_t aaddr = Ah + (uint32_t)((wm * 32 + (lane & 15)) * RS)
                                   + kb + ((lane >> 4) << 4);
            LDSM4(ah[0], aaddr);
            LDSM4(ah[1], aaddr + 16 * RS);
            LDSM4(al[0], aaddr + A_BYTES);
            LDSM4(al[1], aaddr + A_BYTES + 16 * RS);
            const uint32_t baddr = Bh + (uint32_t)((wn * 64 + ((lane >> 4) << 3) + (lane & 7)) * RS)
                                   + kb + (((lane >> 3) & 1) << 4);
#pragma unroll
            for (int g = 0; g < 4; ++g) LDSM4(bb[g], baddr + g * 16 * RS);
            // pass 1: acc += Ah*B  (each acc touched once per pass -> no RAW chain)
#pragma unroll
            for (int mi = 0; mi < 2; ++mi)
#pragma unroll
                for (int ni = 0; ni < 8; ++ni)
                    MMA(acc[mi][ni], ah[mi], (&bb[ni >> 1][(ni & 1) * 2]));
            // pass 2: acc += Al*B
#pragma unroll
            for (int mi = 0; mi < 2; ++mi)
#pragma unroll
                for (int ni = 0; ni < 8; ++ni)
                    MMA(acc[mi][ni], al[mi], (&bb[ni >> 1][(ni & 1) * 2]));
        }
    };

    // ---------------- 3-stage pipelined mainloop, 1 sync per chunk ----------------
    load_chunk(0, 0); CP_COMMIT();
    load_chunk(1, 1); CP_COMMIT();
    for (int ch = 0; ch < NCHUNK; ++ch) {
        CP_WAIT1();            // group ch complete (ch+1 may remain outstanding)
        __syncthreads();       // data visible; stage (ch+2)%3's old compute done
        if (ch + 2 < NCHUNK) load_chunk(ch + 2, (ch + 2) % NSTAGE);
        CP_COMMIT();           // one group per iteration (empty near tail is fine)
        compute_chunk(ch % NSTAGE);
    }

    // ---------------- epilogue: bias add (all compacted rows inside the hex) ----------------
    float bv[16];
#pragma unroll
    for (int ni = 0; ni < 8; ++ni)
#pragma unroll
        for (int j = 0; j < 2; ++j)
            bv[ni * 2 + j] = bias[wn * 64 + ni * 8 + (lane & 3) * 2 + j];

#pragma unroll
    for (int mi = 0; mi < 2; ++mi)
#pragma unroll
        for (int rh = 0; rh < 2; ++rh) {
            const int m = wm * 32 + mi * 16 + (lane >> 2) + rh * 8;
            const int ci = p0 + m;
            if (ci >= NV) continue;
            const int h = g_p2h[ci];
            const int w = hx_wmin(h) + (ci - hx_rowstart(h));
            const int p = h * WW + w;
#pragma unroll
            for (int ni = 0; ni < 8; ++ni)
#pragma unroll
                for (int j = 0; j < 2; ++j) {
                    const int o = wn * 64 + ni * 8 + (lane & 3) * 2 + j;
                    out[((size_t)b * COUT + o) * NPIX + p] =
                        acc[mi][ni][rh * 2 + j] + bv[ni * 2 + j];
                }
        }
}

// ---------------- launch ----------------
extern "C" void kernel_launch(void* const* d_in, const int* in_sizes, int n_in,
                              void* d_out, int out_size) {
    const float* x    = (const float*)d_in[0];
    const float* wgt  = (const float*)d_in[1];
    const float* bias = (const float*)d_in[2];
    float* out = (float*)d_out;
    (void)in_sizes; (void)n_in;

    cudaFuncSetAttribute(hexconv_mma, cudaFuncAttributeMaxDynamicSharedMemorySize, SMEM_BYTES);

    init_tables<<<1, 64>>>();
    zero_out<<<592, 256>>>((float4*)out, out_size / 4);
    split_x_kernel<<<dim3(76, 8, BATCH), 256>>>(x);
    split_w_kernel<<<(NDIR * COUT * CIN + 255) / 256, 256>>>(wgt);

    // compacted implicit GEMM: 29 M-tiles x 32 batches, 2 CTAs/SM, fp16 2-pass
    hexconv_mma<<<dim3(MTILES, BATCH), 256, SMEM_BYTES>>>(bias, out);
}

// round 9
// speedup vs baseline: 2.3066x; 1.2440x over previous
#include <cuda_runtime.h>
#include <cuda_fp16.h>
#include <cstdint>

// ---------------- problem constants ----------------
#define BATCH 32
#define CIN   256
#define COUT  256
#define HH    49
#define WW    49
#define NPIX  2401
#define NDIR  7
#define NV    1801          // valid hex pixels per batch
#define NVP   1856          // padded to 29*64
#define MTILES 29

// ---------------- GEMM tiling ----------------
#define BM 64
#define BN 256
#define BK 32
#define RS 80                      // smem row stride bytes (32 fp16 = 64B + 16B pad)
#define A_BYTES (BM * RS)          // 5120
#define B_BYTES (BN * RS)          // 20480
#define STAGE   (A_BYTES + B_BYTES)           // 25600 (single-precision-pass: A, B)
#define NSTAGE  3
#define SMEM_BYTES (NSTAGE * STAGE)           // 76800 -> 2 CTAs/SM (153.6K <= 228K)
#define NCHUNK  (NDIR * (CIN / BK))           // 56

// ---------------- scratch (static __device__, allocation-guard safe) ----------------
__device__ __align__(16) __half g_xt[(size_t)BATCH * NVP * CIN];
__device__ __align__(16) __half g_w[NDIR * COUT * CIN];
__device__ int g_p2h[NVP];

__constant__ int cDY[NDIR] = {0, 1, 0, -1, -1, 0, 1};
__constant__ int cDX[NDIR] = {0, 0, 1,  1,  0, -1, -1};

// ---------------- hex geometry (closed form) ----------------
__device__ __forceinline__ int hx_wmin(int h) { return h < 24 ? 24 - h : 0; }
__device__ __forceinline__ int hx_wmax(int h) { return h < 24 ? 48 : 72 - h; }
__device__ __forceinline__ int hx_rowstart(int h) {
    return (h <= 24) ? (25 * h + (h * (h - 1)) / 2)
                     : (2101 - ((73 - h) * (74 - h)) / 2);
}

// ---------------- PTX helpers (portable sm_80-level) ----------------
__device__ __forceinline__ void cpa16(uint32_t dst, const void* src, int szbytes) {
    asm volatile("cp.async.cg.shared.global [%0], [%1], 16, %2;"
                 :: "r"(dst), "l"(src), "r"(szbytes) : "memory");
}
#define CP_COMMIT() asm volatile("cp.async.commit_group;" ::: "memory")
#define CP_WAIT1()  asm volatile("cp.async.wait_group 1;" ::: "memory")

#define LDSM4(r, addr) \
    asm volatile("ldmatrix.sync.aligned.m8n8.x4.shared.b16 {%0,%1,%2,%3}, [%4];" \
                 : "=r"((r)[0]), "=r"((r)[1]), "=r"((r)[2]), "=r"((r)[3]) : "r"(addr))

#define MMA(d, a, bp) \
    asm volatile("mma.sync.aligned.m16n8k16.row.col.f32.f16.f16.f32 " \
                 "{%0,%1,%2,%3}, {%4,%5,%6,%7}, {%8,%9}, {%0,%1,%2,%3};" \
                 : "+f"((d)[0]), "+f"((d)[1]), "+f"((d)[2]), "+f"((d)[3]) \
                 : "r"((a)[0]), "r"((a)[1]), "r"((a)[2]), "r"((a)[3]), \
                   "r"((bp)[0]), "r"((bp)[1]))

// ---------------- init: compact-index -> h table ----------------
__global__ void init_tables() {
    const int h = threadIdx.x;
    if (h < 49) {
        const int s = hx_rowstart(h), e = hx_rowstart(h + 1);
        for (int i = s; i < e; ++i) g_p2h[i] = h;
    }
    if (h == 49)
        for (int i = NV; i < NVP; ++i) g_p2h[i] = 0;
}

// ---------------- zero-fill output (masked pixels must be 0; d_out poisoned) ----------------
__global__ void zero_out(float4* __restrict__ o, int n4) {
    const int i = blockIdx.x * blockDim.x + threadIdx.x;
    const int stride = gridDim.x * blockDim.x;
    const float4 z = make_float4(0.f, 0.f, 0.f, 0.f);
    for (int k = i; k < n4; k += stride) o[k] = z;
}

// ---------------- preprocessing ----------------
// x [B,C,H,W] fp32 --(hex compact, transpose, fp16 round)--> xt [b][cidx][c]
__global__ void split_x_kernel(const float* __restrict__ x) {
    __shared__ float t[32][33];
    const int pt = blockIdx.x, ct = blockIdx.y, b = blockIdx.z;
    const int p00 = pt * 32, c00 = ct * 32;
    const int tx = threadIdx.x & 31;
    const int ty = threadIdx.x >> 5;

#pragma unroll
    for (int k = 0; k < 4; ++k) {
        const int c = c00 + ty + k * 8;
        const int p = p00 + tx;
        float v = 0.f;
        if (p < NPIX) v = x[((size_t)b * CIN + c) * NPIX + p];
        t[ty + k * 8][tx] = v;
    }
    __syncthreads();
#pragma unroll
    for (int k = 0; k < 4; ++k) {
        const int p = p00 + ty + k * 8;
        if (p >= NPIX) continue;
        const int h = p / WW, w = p - (p / WW) * WW;
        if (w < hx_wmin(h) || w > hx_wmax(h)) continue;   // outside hex: drop
        const int cidx = hx_rowstart(h) + w - hx_wmin(h);
        const int c = c00 + tx;
        g_xt[((size_t)b * NVP + cidx) * CIN + c] = __float2half(t[tx][ty + k * 8]);
    }
}

// weight [O,C,7] fp32 -> [n][o][c] fp16
__global__ void split_w_kernel(const float* __restrict__ w) {
    const int idx = blockIdx.x * blockDim.x + threadIdx.x;
    if (idx >= NDIR * COUT * CIN) return;
    const int c = idx & 255;
    const int o = (idx >> 8) & 255;
    const int n = idx >> 16;
    g_w[idx] = __float2half(w[o * (CIN * NDIR) + c * NDIR + n]);
}

// ---------------- main warp-MMA implicit-GEMM kernel (compacted M, 1-pass fp16) ----------------
__global__ __launch_bounds__(256, 2)
void hexconv_mma(const float* __restrict__ bias, float* __restrict__ out) {
    extern __shared__ char smem[];
    const uint32_t sb = (uint32_t)__cvta_generic_to_shared(smem);
    const int tid  = threadIdx.x;
    const int lane = tid & 31;
    const int wid  = tid >> 5;
    const int wm   = wid & 1;      // 2 M groups of 32
    const int wn   = wid >> 1;     // 4 N groups of 64
    const int p0   = blockIdx.x * BM;   // compact-pixel tile base
    const int b    = blockIdx.y;

    // A-load geometry: thread -> (row am = tid/4, 16B chunk akc = tid%4)
    const int am  = tid >> 2;
    const int akc = tid & 3;
    const int ai  = p0 + am;            // compact index (< NVP)
    const bool aiv = (ai < NV);
    const int ah_ = g_p2h[ai];
    const int aw_ = hx_wmin(ah_) + (ai - hx_rowstart(ah_));

    float acc[2][8][4];
#pragma unroll
    for (int i = 0; i < 2; ++i)
#pragma unroll
        for (int j = 0; j < 8; ++j)
#pragma unroll
            for (int r = 0; r < 4; ++r) acc[i][j][r] = 0.f;

    auto load_chunk = [&](int ch, int s) {
        const int nd = ch >> 3;
        const int c0 = (ch & 7) << 5;
        const uint32_t st = sb + (uint32_t)s * STAGE;
        // A: hex-shifted neighbor, zero-filled when invalid
        const int hh = ah_ + cDY[nd];
        const int ww = aw_ + cDX[nd];
        const bool hv = ((unsigned)hh < HH);
        const int wmn = hv ? hx_wmin(hh) : 0;
        const bool av = aiv && hv && (ww >= wmn) && (ww <= (hv ? hx_wmax(hh) : -1));
        const int src = av ? (hx_rowstart(hh) + ww - wmn) : 0;
        const size_t abase = ((size_t)b * NVP + src) * CIN + c0 + akc * 8;
        cpa16(st + am * RS + akc * 16, g_xt + abase, av ? 16 : 0);
        // B: row o = tid, 64B contiguous k
        const size_t bbase = ((size_t)nd * COUT + tid) * CIN + c0;
        const uint32_t bdst = st + A_BYTES + tid * RS;
#pragma unroll
        for (int j = 0; j < 4; ++j)
            cpa16(bdst + j * 16, g_w + bbase + j * 8, 16);
    };

    auto compute_chunk = [&](int s) {
        const uint32_t st = sb + (uint32_t)s * STAGE;
        const uint32_t Ah = st;
        const uint32_t Bh = st + A_BYTES;
#pragma unroll
        for (int ks = 0; ks < 2; ++ks) {
            const int kb = ks * 32;   // 16 fp16 = 32 bytes
            uint32_t ah[2][4], bb[4][4];
            const uint32_t aaddr = Ah + (uint32_t)((wm * 32 + (lane & 15)) * RS)
                                   + kb + ((lane >> 4) << 4);
            LDSM4(ah[0], aaddr);
            LDSM4(ah[1], aaddr + 16 * RS);
            const uint32_t baddr = Bh + (uint32_t)((wn * 64 + ((lane >> 4) << 3) + (lane & 7)) * RS)
                                   + kb + (((lane >> 3) & 1) << 4);
#pragma unroll
            for (int g = 0; g < 4; ++g) LDSM4(bb[g], baddr + g * 16 * RS);
            // single pass: acc += A*B (each acc touched once per k-step)
#pragma unroll
            for (int mi = 0; mi < 2; ++mi)
#pragma unroll
                for (int ni = 0; ni < 8; ++ni)
                    MMA(acc[mi][ni], ah[mi], (&bb[ni >> 1][(ni & 1) * 2]));
        }
    };

    // ---------------- 3-stage pipelined mainloop, 1 sync per chunk ----------------
    load_chunk(0, 0); CP_COMMIT();
    load_chunk(1, 1); CP_COMMIT();
    for (int ch = 0; ch < NCHUNK; ++ch) {
        CP_WAIT1();            // group ch complete (ch+1 may remain outstanding)
        __syncthreads();       // data visible; stage (ch+2)%3's old compute done
        if (ch + 2 < NCHUNK) load_chunk(ch + 2, (ch + 2) % NSTAGE);
        CP_COMMIT();           // one group per iteration (empty near tail is fine)
        compute_chunk(ch % NSTAGE);
    }

    // ---------------- epilogue: bias add (all compacted rows inside the hex) ----------------
    float bv[16];
#pragma unroll
    for (int ni = 0; ni < 8; ++ni)
#pragma unroll
        for (int j = 0; j < 2; ++j)
            bv[ni * 2 + j] = bias[wn * 64 + ni * 8 + (lane & 3) * 2 + j];

#pragma unroll
    for (int mi = 0; mi < 2; ++mi)
#pragma unroll
        for (int rh = 0; rh < 2; ++rh) {
            const int m = wm * 32 + mi * 16 + (lane >> 2) + rh * 8;
            const int ci = p0 + m;
            if (ci >= NV) continue;
            const int h = g_p2h[ci];
            const int w = hx_wmin(h) + (ci - hx_rowstart(h));
            const int p = h * WW + w;
#pragma unroll
            for (int ni = 0; ni < 8; ++ni)
#pragma unroll
                for (int j = 0; j < 2; ++j) {
                    const int o = wn * 64 + ni * 8 + (lane & 3) * 2 + j;
                    out[((size_t)b * COUT + o) * NPIX + p] =
                        acc[mi][ni][rh * 2 + j] + bv[ni * 2 + j];
                }
        }
}

// ---------------- launch ----------------
extern "C" void kernel_launch(void* const* d_in, const int* in_sizes, int n_in,
                              void* d_out, int out_size) {
    const float* x    = (const float*)d_in[0];
    const float* wgt  = (const float*)d_in[1];
    const float* bias = (const float*)d_in[2];
    float* out = (float*)d_out;
    (void)in_sizes; (void)n_in;

    cudaFuncSetAttribute(hexconv_mma, cudaFuncAttributeMaxDynamicSharedMemorySize, SMEM_BYTES);

    init_tables<<<1, 64>>>();
    zero_out<<<592, 256>>>((float4*)out, out_size / 4);
    split_x_kernel<<<dim3(76, 8, BATCH), 256>>>(x);
    split_w_kernel<<<(NDIR * COUT * CIN + 255) / 256, 256>>>(wgt);

    // compacted implicit GEMM: 29 M-tiles x 32 batches, 2 CTAs/SM, fp16 single-pass
    hexconv_mma<<<dim3(MTILES, BATCH), 256, SMEM_BYTES>>>(bias, out);
}